// round 11
// baseline (speedup 1.0000x reference)
#include <cuda_runtime.h>
#include <cuda_bf16.h>
#include <cstdint>

// Embedding gather: out[i, :] = table[indices[i], :]
// indices: int32 [819200], table: fp32 [1M, 64], out: fp32 [819200, 64].
// 8 lanes per row; each lane moves 32B via a native 256-bit load
// (ld.global.nc.L2::evict_last.v8.b32). Unroll 4 rows per thread (quarters
// of the row space) -> 4 independent in-flight 32B gathers per thread with
// half the LDG instruction count of the float4 variant (less L1tex queue
// contention). Streaming 16B stores keep L2 reserved for table rows.

struct v8 { uint32_t x0,x1,x2,x3,x4,x5,x6,x7; };

__device__ __forceinline__ v8 ldg256_evict_last(const void* p) {
    v8 v;
    asm volatile("ld.global.nc.L2::evict_last.v8.b32 {%0,%1,%2,%3,%4,%5,%6,%7}, [%8];"
                 : "=r"(v.x0), "=r"(v.x1), "=r"(v.x2), "=r"(v.x3),
                   "=r"(v.x4), "=r"(v.x5), "=r"(v.x6), "=r"(v.x7)
                 : "l"(p));
    return v;
}

__device__ __forceinline__ void stcs256(void* p, const v8& v) {
    float4 a, b;
    a.x = __uint_as_float(v.x0); a.y = __uint_as_float(v.x1);
    a.z = __uint_as_float(v.x2); a.w = __uint_as_float(v.x3);
    b.x = __uint_as_float(v.x4); b.y = __uint_as_float(v.x5);
    b.z = __uint_as_float(v.x6); b.w = __uint_as_float(v.x7);
    __stcs((float4*)p, a);
    __stcs((float4*)p + 1, b);
}

__global__ void __launch_bounds__(256)
emb_gather_u4_v8_kernel(const int* __restrict__ idx,
                        const char* __restrict__ table,
                        char* __restrict__ out,
                        int nrows, int quarter) {
    int t = blockIdx.x * blockDim.x + threadIdx.x;
    int row = t >> 3;          // 8 lanes per row
    int lane = t & 7;          // each lane owns 32B of the 256B row
    if (row >= quarter) return;

    int r0 = row;
    int r1 = row + quarter;
    int r2 = row + 2 * quarter;
    int r3 = row + 3 * quarter;

    // Batch independent index loads (coalesced)
    int i0 = __ldg(&idx[r0]);
    int i1 = __ldg(&idx[r1]);
    int i2 = (r2 < nrows) ? __ldg(&idx[r2]) : 0;
    int i3 = (r3 < nrows) ? __ldg(&idx[r3]) : 0;

    size_t off = (size_t)lane * 32;

    // Batch independent random 32B table loads: MLP = 4
    v8 v0 = ldg256_evict_last(table + (size_t)i0 * 256 + off);
    v8 v1 = ldg256_evict_last(table + (size_t)i1 * 256 + off);
    v8 v2 = ldg256_evict_last(table + (size_t)i2 * 256 + off);
    v8 v3 = ldg256_evict_last(table + (size_t)i3 * 256 + off);

    // Streaming stores — output is write-once, don't pollute L2
    stcs256(out + (size_t)r0 * 256 + off, v0);
    stcs256(out + (size_t)r1 * 256 + off, v1);
    if (r2 < nrows) stcs256(out + (size_t)r2 * 256 + off, v2);
    if (r3 < nrows) stcs256(out + (size_t)r3 * 256 + off, v3);
}

extern "C" void kernel_launch(void* const* d_in, const int* in_sizes, int n_in,
                              void* d_out, int out_size) {
    // Identify inputs by element count so ordering can't break us.
    const void* p_idx = d_in[0];
    const void* p_tab = d_in[1];
    int n_idx = in_sizes[0];
    if (n_in >= 2 && in_sizes[0] > in_sizes[1]) {
        p_tab = d_in[0];
        p_idx = d_in[1];
        n_idx = in_sizes[1];
    }

    const int*  idx = (const int*)p_idx;      // indices, int32, 819200 elems
    const char* tab = (const char*)p_tab;     // table, fp32 [1M,64] = 256B rows
    char*       out = (char*)d_out;

    int nrows = n_idx;                        // 819200
    int quarter = (nrows + 3) / 4;            // rows handled per unroll slot
    long long total_threads = (long long)quarter * 8;
    int block = 256;
    int grid = (int)((total_threads + block - 1) / block);

    emb_gather_u4_v8_kernel<<<grid, block>>>(idx, tab, out, nrows, quarter);
}

// round 12
// speedup vs baseline: 1.0280x; 1.0280x over previous
#include <cuda_runtime.h>
#include <cuda_bf16.h>
#include <cstdint>

// Embedding gather: out[i, :] = table[indices[i], :]
// indices: int32 [819200], table: fp32 [1M, 64] (256B rows), out same rows.
// 8 lanes per row; each lane owns 32B. Table loads stay 128-bit (best L1tex
// wavefront economics for random gathers — LDG.256 regressed) with
// L2::evict_last policy; each lane's 32B is written with ONE 256-bit
// streaming store (st.global.cs.v8.b32): half the store instruction count,
// same coalescing. Unroll 4 rows/thread -> 8 independent loads in flight.

__device__ __forceinline__ float4 ldg_evict_last(const float4* p, unsigned long long pol) {
    float4 v;
    asm volatile("ld.global.nc.L2::cache_hint.v4.f32 {%0,%1,%2,%3}, [%4], %5;"
                 : "=f"(v.x), "=f"(v.y), "=f"(v.z), "=f"(v.w)
                 : "l"(p), "l"(pol));
    return v;
}

__device__ __forceinline__ void stcs256(void* p, const float4& a, const float4& b) {
    asm volatile("st.global.cs.v8.b32 [%0], {%1,%2,%3,%4,%5,%6,%7,%8};"
                 :: "l"(p),
                    "f"(a.x), "f"(a.y), "f"(a.z), "f"(a.w),
                    "f"(b.x), "f"(b.y), "f"(b.z), "f"(b.w)
                 : "memory");
}

__global__ void __launch_bounds__(256)
emb_gather_u4_s256_kernel(const int* __restrict__ idx,
                          const float4* __restrict__ table,
                          char* __restrict__ out,
                          int nrows, int quarter) {
    int t = blockIdx.x * blockDim.x + threadIdx.x;
    int row = t >> 3;          // 8 lanes per row
    int lane = t & 7;          // each lane owns 32B = 2 float4 slots
    if (row >= quarter) return;

    unsigned long long pol;
    asm volatile("createpolicy.fractional.L2::evict_last.b64 %0, 1.0;" : "=l"(pol));

    int r0 = row;
    int r1 = row + quarter;
    int r2 = row + 2 * quarter;
    int r3 = row + 3 * quarter;

    // Batch independent index loads (broadcast within 8-lane groups)
    int i0 = __ldg(&idx[r0]);
    int i1 = __ldg(&idx[r1]);
    int i2 = (r2 < nrows) ? __ldg(&idx[r2]) : 0;
    int i3 = (r3 < nrows) ? __ldg(&idx[r3]) : 0;

    int slot = lane * 2;       // float4 slot within the 16-slot row

    // 8 independent 128-bit random table loads in flight
    float4 a0 = ldg_evict_last(&table[(size_t)i0 * 16 + slot],     pol);
    float4 b0 = ldg_evict_last(&table[(size_t)i0 * 16 + slot + 1], pol);
    float4 a1 = ldg_evict_last(&table[(size_t)i1 * 16 + slot],     pol);
    float4 b1 = ldg_evict_last(&table[(size_t)i1 * 16 + slot + 1], pol);
    float4 a2 = ldg_evict_last(&table[(size_t)i2 * 16 + slot],     pol);
    float4 b2 = ldg_evict_last(&table[(size_t)i2 * 16 + slot + 1], pol);
    float4 a3 = ldg_evict_last(&table[(size_t)i3 * 16 + slot],     pol);
    float4 b3 = ldg_evict_last(&table[(size_t)i3 * 16 + slot + 1], pol);

    size_t off = (size_t)lane * 32;

    // 256-bit streaming stores — write-once output, don't pollute L2
    stcs256(out + (size_t)r0 * 256 + off, a0, b0);
    stcs256(out + (size_t)r1 * 256 + off, a1, b1);
    if (r2 < nrows) stcs256(out + (size_t)r2 * 256 + off, a2, b2);
    if (r3 < nrows) stcs256(out + (size_t)r3 * 256 + off, a3, b3);
}

extern "C" void kernel_launch(void* const* d_in, const int* in_sizes, int n_in,
                              void* d_out, int out_size) {
    // Identify inputs by element count so ordering can't break us.
    const void* p_idx = d_in[0];
    const void* p_tab = d_in[1];
    int n_idx = in_sizes[0];
    if (n_in >= 2 && in_sizes[0] > in_sizes[1]) {
        p_tab = d_in[0];
        p_idx = d_in[1];
        n_idx = in_sizes[1];
    }

    const int*    idx = (const int*)p_idx;      // indices, int32, 819200 elems
    const float4* tab = (const float4*)p_tab;   // table, fp32 [1M,64]
    char*         out = (char*)d_out;

    int nrows = n_idx;                          // 819200
    int quarter = (nrows + 3) / 4;              // rows per unroll slot
    long long total_threads = (long long)quarter * 8;
    int block = 256;
    int grid = (int)((total_threads + block - 1) / block);

    emb_gather_u4_s256_kernel<<<grid, block>>>(idx, tab, out, nrows, quarter);
}